// round 1
// baseline (speedup 1.0000x reference)
#include <cuda_runtime.h>
#include <cstdint>
#include <math.h>

// Problem dims
#define PP 81
#define EE 256
#define HH 4096
#define G4 16384          // 4*HH

// Main-loop config
#define NB 128            // persistent blocks (<= 148 SMs -> all co-resident)
#define NT 512            // threads per block (16 warps)
#define UPB 32            // units per block = HH/NB
#define ROWS_PER_BLK 128  // 4 gates * UPB

// ---------------- scratch (static device allocations are allowed) ----------
__device__ float d_Mt[(size_t)G4 * HH];   // 256 MB: Mt[k][j] = W[E+j][k] + U[j][k]
__device__ float d_X[(size_t)PP * G4];    // 5.3 MB: X[t][k] = b[k] + x_t @ W[:E]
__device__ float d_hbuf[2][HH];           // ping-pong hidden state
__device__ unsigned d_bar_count;          // grid barrier
__device__ unsigned d_bar_gen;

// ---------------- kernel A: build Mt = (W[E:,:] + U)^T ---------------------
__global__ void build_Mt_kernel(const float* __restrict__ W,
                                const float* __restrict__ U) {
    __shared__ float tile[32][33];
    int k0 = blockIdx.x * 32;   // output-column index in z (row of Mt)
    int j0 = blockIdx.y * 32;   // hidden index (col of Mt)
    #pragma unroll
    for (int r = threadIdx.y; r < 32; r += 8) {
        int j = j0 + r;
        int k = k0 + threadIdx.x;
        tile[r][threadIdx.x] = W[(size_t)(EE + j) * G4 + k] + U[(size_t)j * G4 + k];
    }
    __syncthreads();
    #pragma unroll
    for (int r = threadIdx.y; r < 32; r += 8) {
        int k = k0 + r;
        int j = j0 + threadIdx.x;
        d_Mt[(size_t)k * HH + j] = tile[threadIdx.x][r];
    }
}

// ---------------- kernel B: X[t][k] = b[k] + sum_e h_enc[t][e]*W[e][k] -----
__global__ void build_X_kernel(const float* __restrict__ h_enc,
                               const float* __restrict__ W,
                               const float* __restrict__ b) {
    __shared__ float xs[EE];
    int t = blockIdx.y;
    for (int e = threadIdx.x; e < EE; e += 256) xs[e] = h_enc[t * EE + e];
    __syncthreads();
    int k = blockIdx.x * 256 + threadIdx.x;
    float acc = b[k];
    #pragma unroll 8
    for (int e = 0; e < EE; e++) acc = fmaf(xs[e], W[(size_t)e * G4 + k], acc);
    d_X[(size_t)t * G4 + k] = acc;
}

// ---------------- kernel C: h_buf[0] = h0 ----------------------------------
__global__ void init_h_kernel(const float* __restrict__ h0) {
    int i = blockIdx.x * 256 + threadIdx.x;
    if (i < HH) d_hbuf[0][i] = h0[i];
}

// ---------------- grid barrier (spin, all blocks resident) -----------------
__device__ __forceinline__ void grid_barrier() {
    __syncthreads();
    if (threadIdx.x == 0) {
        volatile unsigned* vgen = &d_bar_gen;
        unsigned gen = *vgen;
        __threadfence();                       // flush this block's writes
        if (atomicAdd(&d_bar_count, 1u) == NB - 1) {
            d_bar_count = 0;
            __threadfence();
            *vgen = gen + 1;                   // release
        } else {
            while (*vgen == gen) { }           // acquire spin
            __threadfence();
        }
    }
    __syncthreads();
}

// ---------------- kernel D: persistent sequential LSTM loop ----------------
__global__ void __launch_bounds__(NT, 1)
lstm_loop_kernel(float* __restrict__ orders) {
    __shared__ float h_sh[HH];                 // 16 KB
    __shared__ float z_sh[ROWS_PER_BLK];

    const int tid  = threadIdx.x;
    const int warp = tid >> 5;
    const int lane = tid & 31;
    const int ub   = blockIdx.x * UPB;         // first unit owned by this block

    float c_reg = 0.0f;                        // cell state for unit ub+tid (tid<UPB)

    for (int t = 0; t < PP; t++) {
        const float* __restrict__ hg = d_hbuf[t & 1];

        // load current h into smem (coalesced float4)
        {
            float4* h4s = (float4*)h_sh;
            const float4* hg4 = (const float4*)hg;
            #pragma unroll
            for (int i = tid; i < HH / 4; i += NT) h4s[i] = hg4[i];
        }
        __syncthreads();

        // emit pre-update h
        if (tid < UPB) orders[(size_t)t * HH + ub + tid] = h_sh[ub + tid];

        // 128 dot products: row r = q*UPB + u maps to z index q*HH + ub + u
        for (int r = warp; r < ROWS_PER_BLK; r += NT / 32) {
            int q = r >> 5;
            int u = r & 31;
            const float4* __restrict__ M4 =
                (const float4*)(d_Mt + (size_t)(q * HH + ub + u) * HH);
            const float4* __restrict__ h4 = (const float4*)h_sh;
            float acc0 = 0.0f, acc1 = 0.0f;
            #pragma unroll 8
            for (int i = lane; i < HH / 4; i += 32) {
                float4 m = M4[i];
                float4 hv = h4[i];
                acc0 = fmaf(m.x, hv.x, acc0);
                acc1 = fmaf(m.y, hv.y, acc1);
                acc0 = fmaf(m.z, hv.z, acc0);
                acc1 = fmaf(m.w, hv.w, acc1);
            }
            float acc = acc0 + acc1;
            #pragma unroll
            for (int s = 16; s; s >>= 1) acc += __shfl_xor_sync(0xFFFFFFFFu, acc, s);
            if (lane == 0) z_sh[r] = acc;
        }
        __syncthreads();

        // gate math + state update (one thread per unit)
        if (tid < UPB) {
            int u = tid;
            const float* Xt = d_X + (size_t)t * G4;
            float zi = z_sh[0 * UPB + u] + Xt[0 * HH + ub + u];
            float zf = z_sh[1 * UPB + u] + Xt[1 * HH + ub + u];
            float zg = z_sh[2 * UPB + u] + Xt[2 * HH + ub + u];
            float zo = z_sh[3 * UPB + u] + Xt[3 * HH + ub + u];
            float gi = 1.0f / (1.0f + expf(-zi));
            float gf = 1.0f / (1.0f + expf(-zf));
            float go = 1.0f / (1.0f + expf(-zo));
            float cn = gf * c_reg + gi * zg;   // linear candidate (activation=None)
            float hn = go * cn;                // linear output
            c_reg = cn;
            d_hbuf[(t + 1) & 1][ub + u] = hn;
        }

        grid_barrier();
    }
}

// ---------------- launch ----------------------------------------------------
extern "C" void kernel_launch(void* const* d_in, const int* in_sizes, int n_in,
                              void* d_out, int out_size) {
    const float* h_enc = (const float*)d_in[0];  // [81,256]
    const float* h0    = (const float*)d_in[1];  // [4096]
    const float* W     = (const float*)d_in[2];  // [4352,16384]
    const float* U     = (const float*)d_in[3];  // [4096,16384]
    const float* b     = (const float*)d_in[4];  // [16384]
    float* orders = (float*)d_out;               // [81,4096]

    build_Mt_kernel<<<dim3(G4 / 32, HH / 32), dim3(32, 8)>>>(W, U);
    build_X_kernel<<<dim3(G4 / 256, PP), 256>>>(h_enc, W, b);
    init_h_kernel<<<(HH + 255) / 256, 256>>>(h0);
    lstm_loop_kernel<<<NB, NT>>>(orders);
}

// round 2
// speedup vs baseline: 1.4793x; 1.4793x over previous
#include <cuda_runtime.h>
#include <cuda_fp16.h>
#include <cstdint>
#include <math.h>

// Problem dims
#define PP 81
#define EE 256
#define HH 4096
#define G4 16384          // 4*HH

// Main-loop config
#define NB 128            // persistent blocks (<= 148 SMs -> all co-resident)
#define NT 512            // threads per block (16 warps)
#define UPB 32            // units per block = HH/NB
#define ROWS_PER_BLK 128  // 4 gates * UPB

// ---------------- scratch (static device allocations are allowed) ----------
__device__ __half d_Mt[(size_t)G4 * HH];  // 128 MB: Mt[k][j] = W[E+j][k] + U[j][k]
__device__ float  d_X[(size_t)PP * G4];   // 5.3 MB: X[t][k] = b[k] + x_t @ W[:E]
__device__ float  d_hbuf[2][HH];          // ping-pong hidden state
__device__ unsigned d_bar_count;          // grid barrier
__device__ unsigned d_bar_gen;

// ---------------- kernel A: build Mt = (W[E:,:] + U)^T  (fp16) -------------
__global__ void build_Mt_kernel(const float* __restrict__ W,
                                const float* __restrict__ U) {
    __shared__ float tile[32][33];
    int k0 = blockIdx.x * 32;   // output-column index in z (row of Mt)
    int j0 = blockIdx.y * 32;   // hidden index (col of Mt)
    #pragma unroll
    for (int r = threadIdx.y; r < 32; r += 8) {
        int j = j0 + r;
        int k = k0 + threadIdx.x;
        tile[r][threadIdx.x] = W[(size_t)(EE + j) * G4 + k] + U[(size_t)j * G4 + k];
    }
    __syncthreads();
    #pragma unroll
    for (int r = threadIdx.y; r < 32; r += 8) {
        int k = k0 + r;
        int j = j0 + threadIdx.x;
        d_Mt[(size_t)k * HH + j] = __float2half_rn(tile[threadIdx.x][r]);
    }
}

// ---------------- kernel B: X[t][k] = b[k] + sum_e h_enc[t][e]*W[e][k] -----
__global__ void build_X_kernel(const float* __restrict__ h_enc,
                               const float* __restrict__ W,
                               const float* __restrict__ b) {
    __shared__ float xs[EE];
    int t = blockIdx.y;
    for (int e = threadIdx.x; e < EE; e += 256) xs[e] = h_enc[t * EE + e];
    __syncthreads();
    int k = blockIdx.x * 256 + threadIdx.x;
    float acc = b[k];
    #pragma unroll 8
    for (int e = 0; e < EE; e++) acc = fmaf(xs[e], W[(size_t)e * G4 + k], acc);
    d_X[(size_t)t * G4 + k] = acc;
}

// ---------------- kernel C: h_buf[0] = h0 ----------------------------------
__global__ void init_h_kernel(const float* __restrict__ h0) {
    int i = blockIdx.x * 256 + threadIdx.x;
    if (i < HH) d_hbuf[0][i] = h0[i];
}

// ---------------- grid barrier (spin, all blocks resident) -----------------
__device__ __forceinline__ void grid_barrier() {
    __syncthreads();
    if (threadIdx.x == 0) {
        volatile unsigned* vgen = &d_bar_gen;
        unsigned gen = *vgen;
        __threadfence();                       // flush this block's writes
        if (atomicAdd(&d_bar_count, 1u) == NB - 1) {
            d_bar_count = 0;
            __threadfence();
            *vgen = gen + 1;                   // release
        } else {
            while (*vgen == gen) { }           // acquire spin
            __threadfence();
        }
    }
    __syncthreads();
}

// ---------------- kernel D: persistent sequential LSTM loop ----------------
__global__ void __launch_bounds__(NT, 1)
lstm_loop_kernel(float* __restrict__ orders) {
    __shared__ float h_sh[HH];                 // 16 KB
    __shared__ float z_sh[ROWS_PER_BLK];

    const int tid  = threadIdx.x;
    const int warp = tid >> 5;
    const int lane = tid & 31;
    const int ub   = blockIdx.x * UPB;         // first unit owned by this block

    float c_reg = 0.0f;                        // cell state for unit ub+tid (tid<UPB)

    for (int t = 0; t < PP; t++) {
        const float* __restrict__ hg = d_hbuf[t & 1];

        // load current h into smem (coalesced float4)
        {
            float4* h4s = (float4*)h_sh;
            const float4* hg4 = (const float4*)hg;
            #pragma unroll
            for (int i = tid; i < HH / 4; i += NT) h4s[i] = hg4[i];
        }
        __syncthreads();

        // emit pre-update h
        if (tid < UPB) orders[(size_t)t * HH + ub + tid] = h_sh[ub + tid];

        // 128 dot products: row r = q*UPB + u maps to z index q*HH + ub + u
        for (int r = warp; r < ROWS_PER_BLK; r += NT / 32) {
            int q = r >> 5;
            int u = r & 31;
            // row of Mt in fp16: 4096 halves. Each lane loads float2 = 4 halves,
            // coalesced 256B/warp; h_sh read as float4[i], i = lane+32k -> no
            // bank conflicts. fp32 accumulation.
            const float2* __restrict__ M2 =
                (const float2*)(d_Mt + (size_t)(q * HH + ub + u) * HH);
            const float4* __restrict__ h4 = (const float4*)h_sh;
            float acc0 = 0.0f, acc1 = 0.0f;
            #pragma unroll 8
            for (int i = lane; i < HH / 4; i += 32) {
                float2 mr = M2[i];                       // 4 halves
                const half2* mh = (const half2*)&mr;
                float2 m0 = __half22float2(mh[0]);
                float2 m1 = __half22float2(mh[1]);
                float4 hv = h4[i];
                acc0 = fmaf(m0.x, hv.x, acc0);
                acc1 = fmaf(m0.y, hv.y, acc1);
                acc0 = fmaf(m1.x, hv.z, acc0);
                acc1 = fmaf(m1.y, hv.w, acc1);
            }
            float acc = acc0 + acc1;
            #pragma unroll
            for (int s = 16; s; s >>= 1) acc += __shfl_xor_sync(0xFFFFFFFFu, acc, s);
            if (lane == 0) z_sh[r] = acc;
        }
        __syncthreads();

        // gate math + state update (one thread per unit)
        if (tid < UPB) {
            int u = tid;
            const float* Xt = d_X + (size_t)t * G4;
            float zi = z_sh[0 * UPB + u] + Xt[0 * HH + ub + u];
            float zf = z_sh[1 * UPB + u] + Xt[1 * HH + ub + u];
            float zg = z_sh[2 * UPB + u] + Xt[2 * HH + ub + u];
            float zo = z_sh[3 * UPB + u] + Xt[3 * HH + ub + u];
            float gi = 1.0f / (1.0f + expf(-zi));
            float gf = 1.0f / (1.0f + expf(-zf));
            float go = 1.0f / (1.0f + expf(-zo));
            float cn = gf * c_reg + gi * zg;   // linear candidate (activation=None)
            float hn = go * cn;                // linear output
            c_reg = cn;
            d_hbuf[(t + 1) & 1][ub + u] = hn;
        }

        grid_barrier();
    }
}

// ---------------- launch ----------------------------------------------------
extern "C" void kernel_launch(void* const* d_in, const int* in_sizes, int n_in,
                              void* d_out, int out_size) {
    const float* h_enc = (const float*)d_in[0];  // [81,256]
    const float* h0    = (const float*)d_in[1];  // [4096]
    const float* W     = (const float*)d_in[2];  // [4352,16384]
    const float* U     = (const float*)d_in[3];  // [4096,16384]
    const float* b     = (const float*)d_in[4];  // [16384]
    float* orders = (float*)d_out;               // [81,4096]

    build_Mt_kernel<<<dim3(G4 / 32, HH / 32), dim3(32, 8)>>>(W, U);
    build_X_kernel<<<dim3(G4 / 256, PP), 256>>>(h_enc, W, b);
    init_h_kernel<<<(HH + 255) / 256, 256>>>(h0);
    lstm_loop_kernel<<<NB, NT>>>(orders);
}

// round 3
// speedup vs baseline: 1.6731x; 1.1310x over previous
#include <cuda_runtime.h>
#include <cuda_fp16.h>
#include <cstdint>
#include <math.h>

// Problem dims
#define PP 81
#define EE 256
#define HH 4096
#define G4 16384          // 4*HH

// Main-loop config
#define NB 128            // persistent blocks (<= 148 SMs -> all co-resident)
#define NT 512            // threads per block (16 warps)
#define UPB 32            // units per block = HH/NB
#define ROWS_PER_BLK 128  // 4 gates * UPB

// ---------------- scratch (static device allocations are allowed) ----------
__device__ __half d_Mt[(size_t)G4 * HH];  // 128 MB: Mt[k][j] = W[E+j][k] + U[j][k]
__device__ float  d_X[(size_t)PP * G4];   // 5.3 MB: X[t][k] = b[k] + x_t @ W[:E]
__device__ float  d_hbuf[2][HH];          // ping-pong hidden state
__device__ unsigned d_bar_count;          // grid barrier
__device__ unsigned d_bar_gen;

// ---------------- kernel A: build Mt = (W[E:,:] + U)^T  (fp16) -------------
__global__ void build_Mt_kernel(const float* __restrict__ W,
                                const float* __restrict__ U) {
    __shared__ float tile[32][33];
    int k0 = blockIdx.x * 32;   // output-column index in z (row of Mt)
    int j0 = blockIdx.y * 32;   // hidden index (col of Mt)
    #pragma unroll
    for (int r = threadIdx.y; r < 32; r += 8) {
        int j = j0 + r;
        int k = k0 + threadIdx.x;
        tile[r][threadIdx.x] = W[(size_t)(EE + j) * G4 + k] + U[(size_t)j * G4 + k];
    }
    __syncthreads();
    #pragma unroll
    for (int r = threadIdx.y; r < 32; r += 8) {
        int k = k0 + r;
        int j = j0 + threadIdx.x;
        d_Mt[(size_t)k * HH + j] = __float2half_rn(tile[threadIdx.x][r]);
    }
}

// ---------------- kernel B: X[t][k] = b[k] + sum_e h_enc[t][e]*W[e][k] -----
__global__ void build_X_kernel(const float* __restrict__ h_enc,
                               const float* __restrict__ W,
                               const float* __restrict__ b) {
    __shared__ float xs[EE];
    int t = blockIdx.y;
    for (int e = threadIdx.x; e < EE; e += 256) xs[e] = h_enc[t * EE + e];
    __syncthreads();
    int k = blockIdx.x * 256 + threadIdx.x;
    float acc = b[k];
    #pragma unroll 8
    for (int e = 0; e < EE; e++) acc = fmaf(xs[e], W[(size_t)e * G4 + k], acc);
    d_X[(size_t)t * G4 + k] = acc;
}

// ---------------- kernel C: h_buf[0] = h0 ----------------------------------
__global__ void init_h_kernel(const float* __restrict__ h0) {
    int i = blockIdx.x * 256 + threadIdx.x;
    if (i < HH) d_hbuf[0][i] = h0[i];
}

// ---------------- grid barrier (spin, all blocks resident) -----------------
__device__ __forceinline__ void grid_barrier() {
    __syncthreads();
    if (threadIdx.x == 0) {
        volatile unsigned* vgen = &d_bar_gen;
        unsigned gen = *vgen;
        __threadfence();                       // flush this block's writes
        if (atomicAdd(&d_bar_count, 1u) == NB - 1) {
            d_bar_count = 0;
            __threadfence();
            *vgen = gen + 1;                   // release
        } else {
            while (*vgen == gen) { }           // acquire spin
            __threadfence();
        }
    }
    __syncthreads();
}

// ---------------- kernel D: persistent sequential LSTM loop ----------------
__global__ void __launch_bounds__(NT, 1)
lstm_loop_kernel(float* __restrict__ orders) {
    __shared__ float h_sh[HH];                 // 16 KB
    __shared__ float z_sh[ROWS_PER_BLK];

    const int tid  = threadIdx.x;
    const int warp = tid >> 5;
    const int lane = tid & 31;
    const int ub   = blockIdx.x * UPB;         // first unit owned by this block

    float c_reg = 0.0f;                        // cell state for unit ub+tid (tid<UPB)

    for (int t = 0; t < PP; t++) {
        const float* __restrict__ hg = d_hbuf[t & 1];

        // load current h into smem (coalesced float4)
        {
            float4* h4s = (float4*)h_sh;
            const float4* hg4 = (const float4*)hg;
            #pragma unroll
            for (int i = tid; i < HH / 4; i += NT) h4s[i] = hg4[i];
        }
        __syncthreads();

        // emit pre-update h
        if (tid < UPB) orders[(size_t)t * HH + ub + tid] = h_sh[ub + tid];

        // 128 dot products, 2 rows per warp concurrently (8 rows/warp total).
        // Row r = q*UPB + u maps to z index q*HH + ub + u.
        // Each lane loads uint4 = 8 halves per row (512B/warp/row coalesced);
        // one pair of h float4 reads feeds both rows. fp32 accumulation.
        const float4* __restrict__ h4 = (const float4*)h_sh;
        #pragma unroll
        for (int pr = 0; pr < 4; pr++) {
            const int ra = warp + 32 * pr;
            const int rb = ra + 16;
            const int qa = ra >> 5, ua = ra & 31;
            const int qb = rb >> 5, ubb = rb & 31;
            const uint4* __restrict__ Ma =
                (const uint4*)(d_Mt + (size_t)(qa * HH + ub + ua) * HH);
            const uint4* __restrict__ Mb =
                (const uint4*)(d_Mt + (size_t)(qb * HH + ub + ubb) * HH);

            float a0 = 0.f, a1 = 0.f, b0 = 0.f, b1 = 0.f;
            #pragma unroll 8
            for (int i = lane; i < HH / 8; i += 32) {   // 16 iterations
                uint4 ma = Ma[i];
                uint4 mb = Mb[i];
                float4 hA = h4[2 * i];
                float4 hB = h4[2 * i + 1];
                const half2* pa = (const half2*)&ma;
                const half2* pb = (const half2*)&mb;
                float2 a_0 = __half22float2(pa[0]);
                float2 a_1 = __half22float2(pa[1]);
                float2 a_2 = __half22float2(pa[2]);
                float2 a_3 = __half22float2(pa[3]);
                float2 b_0 = __half22float2(pb[0]);
                float2 b_1 = __half22float2(pb[1]);
                float2 b_2 = __half22float2(pb[2]);
                float2 b_3 = __half22float2(pb[3]);
                a0 = fmaf(a_0.x, hA.x, a0);  a1 = fmaf(a_0.y, hA.y, a1);
                a0 = fmaf(a_1.x, hA.z, a0);  a1 = fmaf(a_1.y, hA.w, a1);
                a0 = fmaf(a_2.x, hB.x, a0);  a1 = fmaf(a_2.y, hB.y, a1);
                a0 = fmaf(a_3.x, hB.z, a0);  a1 = fmaf(a_3.y, hB.w, a1);
                b0 = fmaf(b_0.x, hA.x, b0);  b1 = fmaf(b_0.y, hA.y, b1);
                b0 = fmaf(b_1.x, hA.z, b0);  b1 = fmaf(b_1.y, hA.w, b1);
                b0 = fmaf(b_2.x, hB.x, b0);  b1 = fmaf(b_2.y, hB.y, b1);
                b0 = fmaf(b_3.x, hB.z, b0);  b1 = fmaf(b_3.y, hB.w, b1);
            }
            float accA = a0 + a1;
            float accB = b0 + b1;
            #pragma unroll
            for (int s = 16; s; s >>= 1) {
                accA += __shfl_xor_sync(0xFFFFFFFFu, accA, s);
                accB += __shfl_xor_sync(0xFFFFFFFFu, accB, s);
            }
            if (lane == 0) { z_sh[ra] = accA; z_sh[rb] = accB; }
        }
        __syncthreads();

        // gate math + state update (one thread per unit)
        if (tid < UPB) {
            int u = tid;
            const float* Xt = d_X + (size_t)t * G4;
            float zi = z_sh[0 * UPB + u] + Xt[0 * HH + ub + u];
            float zf = z_sh[1 * UPB + u] + Xt[1 * HH + ub + u];
            float zg = z_sh[2 * UPB + u] + Xt[2 * HH + ub + u];
            float zo = z_sh[3 * UPB + u] + Xt[3 * HH + ub + u];
            float gi = 1.0f / (1.0f + expf(-zi));
            float gf = 1.0f / (1.0f + expf(-zf));
            float go = 1.0f / (1.0f + expf(-zo));
            float cn = gf * c_reg + gi * zg;   // linear candidate (activation=None)
            float hn = go * cn;                // linear output
            c_reg = cn;
            d_hbuf[(t + 1) & 1][ub + u] = hn;
            __threadfence();                   // make h visible device-wide
        }

        grid_barrier();
    }
}

// ---------------- launch ----------------------------------------------------
extern "C" void kernel_launch(void* const* d_in, const int* in_sizes, int n_in,
                              void* d_out, int out_size) {
    const float* h_enc = (const float*)d_in[0];  // [81,256]
    const float* h0    = (const float*)d_in[1];  // [4096]
    const float* W     = (const float*)d_in[2];  // [4352,16384]
    const float* U     = (const float*)d_in[3];  // [4096,16384]
    const float* b     = (const float*)d_in[4];  // [16384]
    float* orders = (float*)d_out;               // [81,4096]

    build_Mt_kernel<<<dim3(G4 / 32, HH / 32), dim3(32, 8)>>>(W, U);
    build_X_kernel<<<dim3(G4 / 256, PP), 256>>>(h_enc, W, b);
    init_h_kernel<<<(HH + 255) / 256, 256>>>(h0);
    lstm_loop_kernel<<<NB, NT>>>(orders);
}